// round 9
// baseline (speedup 1.0000x reference)
#include <cuda_runtime.h>
#include <cuda_fp16.h>
#include <cstdint>
#include <cstddef>

#define BB   32
#define PS   1536
#define TNS  2048
#define NJ   128
#define QK   384
#define NC   200

// ---------------------------------------------------------------------------
// scratch (static device globals; no allocation)
// ---------------------------------------------------------------------------
__device__ __half g_w0hi[(size_t)NJ * TNS];
__device__ __half g_w0lo[(size_t)NJ * TNS];
__device__ __half g_c1hi[(size_t)PS * PS];
__device__ __half g_c1lo[(size_t)PS * PS];
__device__ __half g_h1  [(size_t)BB * NJ * PS];   // hs1^T [b][j][c], fp16
__device__ __half g_h2  [(size_t)BB * PS * NJ];   // hs2   [b][o][j], fp16
__device__ __half g_a1hi[(size_t)BB * NJ * NJ];   // A1^T  [b][k][j]
__device__ __half g_a1lo[(size_t)BB * NJ * NJ];
__device__ float g_sbc [(size_t)BB * PS];
__device__ float g_ssbc[(size_t)BB * PS];
__device__ float g_dotb[(size_t)BB * PS];
__device__ float g_q1 [BB * NJ];
__device__ float g_k1 [BB * NJ];
__device__ float g_wqm[PS];
__device__ float g_wkm[PS];
__device__ float g_bqkm[2];
__device__ float g_hs4[BB * PS];

// ---------------------------------------------------------------------------
// helpers
// ---------------------------------------------------------------------------
__device__ __forceinline__ uint32_t smem_u32(const void* p) {
    uint32_t a;
    asm("{ .reg .u64 t; cvta.to.shared.u64 t, %1; cvt.u32.u64 %0, t; }" : "=r"(a) : "l"(p));
    return a;
}
#define CP_COMMIT() asm volatile("cp.async.commit_group;" ::: "memory")
#define CP_WAIT0()  asm volatile("cp.async.wait_group 0;" ::: "memory")
#define CP_WAIT1()  asm volatile("cp.async.wait_group 1;" ::: "memory")

__device__ __forceinline__ void ld4(uint32_t* r, uint32_t a) {
    asm volatile("ldmatrix.sync.aligned.m8n8.x4.shared.b16 {%0,%1,%2,%3}, [%4];"
        : "=r"(r[0]), "=r"(r[1]), "=r"(r[2]), "=r"(r[3]) : "r"(a));
}
__device__ __forceinline__ void mma16816(float* d, const uint32_t* a, const uint32_t* b) {
    asm volatile(
        "mma.sync.aligned.m16n8k16.row.col.f32.f16.f16.f32 "
        "{%0,%1,%2,%3}, {%4,%5,%6,%7}, {%8,%9}, {%0,%1,%2,%3};"
        : "+f"(d[0]), "+f"(d[1]), "+f"(d[2]), "+f"(d[3])
        : "r"(a[0]), "r"(a[1]), "r"(a[2]), "r"(a[3]), "r"(b[0]), "r"(b[1]));
}

// fp32 -> (hi, lo) fp16 split (standalone pass for weights)
__global__ void k_cvt(const float* __restrict__ s, __half* __restrict__ hi,
                      __half* __restrict__ lo, long n4) {
    long i = (long)blockIdx.x * blockDim.x + threadIdx.x;
    if (i >= n4) return;
    float4 v = ((const float4*)s)[i];
    __half h0 = __float2half_rn(v.x), h1 = __float2half_rn(v.y);
    __half h2 = __float2half_rn(v.z), h3 = __float2half_rn(v.w);
    __half l0 = __float2half_rn(v.x - __half2float(h0));
    __half l1 = __float2half_rn(v.y - __half2float(h1));
    __half l2 = __float2half_rn(v.z - __half2float(h2));
    __half l3 = __float2half_rn(v.w - __half2float(h3));
    __half2 ph0; ph0.x = h0; ph0.y = h1;
    __half2 ph1; ph1.x = h2; ph1.y = h3;
    __half2 pl0; pl0.x = l0; pl0.y = l1;
    __half2 pl1; pl1.x = l2; pl1.y = l3;
    ((__half2*)hi)[i * 2 + 0] = ph0;
    ((__half2*)hi)[i * 2 + 1] = ph1;
    ((__half2*)lo)[i * 2 + 0] = pl0;
    ((__half2*)lo)[i * 2 + 1] = pl1;
}

// ---------------------------------------------------------------------------
// SMEM tile layout: 2 stages x 3 tiles, 128 rows x 128 k (fp16, 256B/row + 16 pad)
// row stride 272B = 68 banks == 4 (mod 32) -> ldmatrix conflict-free
// ---------------------------------------------------------------------------
#define BK    128
#define RSTR  272
#define TILEB (128 * RSTR)     // 34816
#define STG3  (3 * TILEB)      // 104448

__device__ __forceinline__ void load_tile(uint32_t sb, const __half* g, int gstride, int k0) {
    const int t = threadIdx.x;
#pragma unroll
    for (int p = 0; p < 8; p++) {
        int idx = p * 256 + t;
        int row = idx >> 4, ch = idx & 15;
        uint32_t dst = sb + row * RSTR + ch * 16;
        const void* src = g + (size_t)row * gstride + k0 + ch * 8;
        asm volatile("cp.async.cg.shared.global [%0], [%1], 16;" :: "r"(dst), "l"(src));
    }
}

// 2-term MMA over one stage (8 k16 steps), split-A: tile0=Ah, tile1=Al, tile2=B
#define MMA_STAGE_SA(st)                                                         \
    do {                                                                         \
        _Pragma("unroll")                                                        \
        for (int ks = 0; ks < 8; ks++) {                                         \
            const uint32_t klo = ks * 32;                                        \
            uint32_t ah[4][4], bf[2][4];                                         \
            _Pragma("unroll")                                                    \
            for (int mt = 0; mt < 4; mt++) ld4(ah[mt], (st) + 0 * TILEB + aoff[mt] + klo); \
            _Pragma("unroll")                                                    \
            for (int np = 0; np < 2; np++) ld4(bf[np], (st) + 2 * TILEB + boff[np] + klo); \
            _Pragma("unroll")                                                    \
            for (int mt = 0; mt < 4; mt++)                                       \
                _Pragma("unroll")                                                \
                for (int nt = 0; nt < 4; nt++)                                   \
                    mma16816(d[mt][nt], ah[mt], &bf[nt >> 1][(nt & 1) * 2]);     \
            {                                                                    \
                uint32_t al[4][4];                                               \
                _Pragma("unroll")                                                \
                for (int mt = 0; mt < 4; mt++) ld4(al[mt], (st) + 1 * TILEB + aoff[mt] + klo); \
                _Pragma("unroll")                                                \
                for (int mt = 0; mt < 4; mt++)                                   \
                    _Pragma("unroll")                                            \
                    for (int nt = 0; nt < 4; nt++)                               \
                        mma16816(d[mt][nt], al[mt], &bf[nt >> 1][(nt & 1) * 2]); \
            }                                                                    \
        }                                                                        \
    } while (0)

// 2-term MMA, split-B: tile0 = A, tile1 = Bh, tile2 = Bl
#define MMA_STAGE_SB(st)                                                         \
    do {                                                                         \
        _Pragma("unroll")                                                        \
        for (int ks = 0; ks < 8; ks++) {                                         \
            const uint32_t klo = ks * 32;                                        \
            uint32_t af[4][4], bh[2][4];                                         \
            _Pragma("unroll")                                                    \
            for (int mt = 0; mt < 4; mt++) ld4(af[mt], (st) + 0 * TILEB + aoff[mt] + klo); \
            _Pragma("unroll")                                                    \
            for (int np = 0; np < 2; np++) ld4(bh[np], (st) + 1 * TILEB + boff[np] + klo); \
            _Pragma("unroll")                                                    \
            for (int mt = 0; mt < 4; mt++)                                       \
                _Pragma("unroll")                                                \
                for (int nt = 0; nt < 4; nt++)                                   \
                    mma16816(d[mt][nt], af[mt], &bh[nt >> 1][(nt & 1) * 2]);     \
            {                                                                    \
                uint32_t bl[2][4];                                               \
                _Pragma("unroll")                                                \
                for (int np = 0; np < 2; np++) ld4(bl[np], (st) + 2 * TILEB + boff[np] + klo); \
                _Pragma("unroll")                                                \
                for (int mt = 0; mt < 4; mt++)                                   \
                    _Pragma("unroll")                                            \
                    for (int nt = 0; nt < 4; nt++)                               \
                        mma16816(d[mt][nt], af[mt], &bl[nt >> 1][(nt & 1) * 2]); \
            }                                                                    \
        }                                                                        \
    } while (0)

// ---------------------------------------------------------------------------
// GEMM1: D[j, c-tile] = (w0h + w0l)[j,:] . x_fp16[b, c,:]  -> hs1^T fp16
// B (x) fp32 LDG: each ldgB covers 64 k-columns; chunk uses two reg sets.
// ---------------------------------------------------------------------------
__device__ __forceinline__ void ldgB(float4* br, const float* pB, int K, int k0) {
    const int t = threadIdx.x;
#pragma unroll
    for (int p = 0; p < 8; p++) {
        int idx = p * 256 + t;
        int row = idx >> 4, f4 = idx & 15;
        br[p] = *(const float4*)(pB + (size_t)row * K + k0 + f4 * 4);
    }
}
__device__ __forceinline__ void cvt_sts(const float4* br, uint32_t st, uint32_t kb) {
    const int t = threadIdx.x;
#pragma unroll
    for (int p = 0; p < 8; p++) {
        int idx = p * 256 + t;
        int row = idx >> 4, f4 = idx & 15;
        float4 v = br[p];
        __half2 h01 = __floats2half2_rn(v.x, v.y);
        __half2 h23 = __floats2half2_rn(v.z, v.w);
        uint32_t off = (uint32_t)(row * RSTR + kb + f4 * 8);
        asm volatile("st.shared.v2.b32 [%0], {%1,%2};"
            :: "r"(st + 2 * TILEB + off), "r"(*(uint32_t*)&h01), "r"(*(uint32_t*)&h23));
    }
}

__global__ __launch_bounds__(256, 1) void mma_gemm_x(
    const __half* __restrict__ Ah, const __half* __restrict__ Al,
    const float* __restrict__ Bf, long b_bstr,
    int K,
    const float* __restrict__ bias,
    __half* __restrict__ oh,
    long o_bstr, int o_rstr)
{
    extern __shared__ char dsm[];
    const uint32_t sb = smem_u32(dsm);

    const int tid = threadIdx.x;
    const int wid = tid >> 5, lane = tid & 31;
    const int bz = blockIdx.z;
    const int Boff = blockIdx.x * 128;
    const float* pBf = Bf + (size_t)bz * b_bstr + (size_t)Boff * K;

    const int m_base = (wid >> 2) * 64;
    const int n_base = (wid & 3) * 32;
    const int quad = lane >> 3, id8 = lane & 7;

    uint32_t aoff[4], boff[2];
#pragma unroll
    for (int mt = 0; mt < 4; mt++)
        aoff[mt] = (uint32_t)((m_base + mt * 16 + (quad & 1) * 8 + id8) * RSTR + ((quad >> 1) * 8) * 2);
#pragma unroll
    for (int np = 0; np < 2; np++)
        boff[np] = (uint32_t)((n_base + np * 16 + (quad >> 1) * 8 + id8) * RSTR + ((quad & 1) * 8) * 2);

    float d[4][4][4];
#pragma unroll
    for (int mt = 0; mt < 4; mt++)
#pragma unroll
        for (int nt = 0; nt < 4; nt++)
#pragma unroll
            for (int k = 0; k < 4; k++) d[mt][nt][k] = 0.f;

    const int nk = K / BK;
    float4 br0[8], br1[8];

    // prologue: chunk0 + chunk1 staged
    ldgB(br0, pBf, K, 0);
    ldgB(br1, pBf, K, 64);
    cvt_sts(br0, sb, 0);
    cvt_sts(br1, sb, 128);
    load_tile(sb + 0 * TILEB, Ah, K, 0);
    load_tile(sb + 1 * TILEB, Al, K, 0);
    CP_COMMIT();
    ldgB(br0, pBf, K, BK);
    ldgB(br1, pBf, K, BK + 64);
    cvt_sts(br0, sb + STG3, 0);
    cvt_sts(br1, sb + STG3, 128);
    load_tile(sb + STG3 + 0 * TILEB, Ah, K, BK);
    load_tile(sb + STG3 + 1 * TILEB, Al, K, BK);
    CP_COMMIT();
    CP_WAIT1();
    __syncthreads();

    for (int i = 0; i < nk; i++) {
        const uint32_t st = sb + (i & 1) * STG3;
        if (i + 2 < nk) {
            ldgB(br0, pBf, K, (i + 2) * BK);
            ldgB(br1, pBf, K, (i + 2) * BK + 64);
        }

        MMA_STAGE_SA(st);

        __syncthreads();                      // stage (i&1) free
        if (i + 2 < nk) {
            cvt_sts(br0, st, 0);
            cvt_sts(br1, st, 128);
            load_tile(st + 0 * TILEB, Ah, K, (i + 2) * BK);
            load_tile(st + 1 * TILEB, Al, K, (i + 2) * BK);
            CP_COMMIT();
        }
        if (i + 1 < nk) {
            if (i + 2 < nk) CP_WAIT1(); else CP_WAIT0();
            __syncthreads();                  // stage (i+1) ready
        }
    }

    // epilogue: fp16 single
    const int g = lane >> 2, t2 = (lane & 3) * 2;
#pragma unroll
    for (int mt = 0; mt < 4; mt++) {
        const int r0 = m_base + mt * 16 + g;
        const int r1 = r0 + 8;
        const float bv0 = bias ? bias[r0] : 0.f;
        const float bv1 = bias ? bias[r1] : 0.f;
        const size_t base0 = (size_t)bz * o_bstr + (size_t)r0 * o_rstr + Boff;
        const size_t base1 = (size_t)bz * o_bstr + (size_t)r1 * o_rstr + Boff;
#pragma unroll
        for (int nt = 0; nt < 4; nt++) {
            const int col = n_base + nt * 8 + t2;
            *(__half2*)(oh + base0 + col) = __floats2half2_rn(d[mt][nt][0] + bv0, d[mt][nt][1] + bv0);
            *(__half2*)(oh + base1 + col) = __floats2half2_rn(d[mt][nt][2] + bv1, d[mt][nt][3] + bv1);
        }
    }
}

// ---------------------------------------------------------------------------
// generic warp-MMA GEMM, 2-term fp16 split.
//   SPLITB == 0: tiles (Ah, Al, B)   — GEMM2 (weights split)
//   SPLITB == 1: tiles (A, Bh, Bl)   — GEMM3 (A1 split)
//   w1f != nullptr: fused BN-stat + pool epilogue (GEMM3)
// ---------------------------------------------------------------------------
template <int SPLITB>
__global__ __launch_bounds__(256, 1) void mma_gemm(
    const __half* __restrict__ P0, long s0,
    const __half* __restrict__ P1, long s1,
    const __half* __restrict__ P2, long s2,
    int K,
    const float* __restrict__ bias,
    __half* __restrict__ oh,
    long o_bstr, int o_rstr,
    const float* __restrict__ w1f,
    float* __restrict__ sbc, float* __restrict__ ssbc, float* __restrict__ dotb)
{
    extern __shared__ char dsm[];
    const uint32_t sb = smem_u32(dsm);

    const int tid = threadIdx.x;
    const int wid = tid >> 5, lane = tid & 31;
    const int bz = blockIdx.z;
    const int Aoff = blockIdx.x * 128;   // M always tiled

    const __half* p0 = P0 + (size_t)bz * s0 + (size_t)Aoff * K;
    const __half* p1 = P1 + (size_t)bz * s1 + (SPLITB ? 0 : (size_t)Aoff * K);
    const __half* p2 = P2 + (size_t)bz * s2;

    const int m_base = (wid >> 2) * 64;
    const int n_base = (wid & 3) * 32;
    const int quad = lane >> 3, id8 = lane & 7;

    uint32_t aoff[4], boff[2];
#pragma unroll
    for (int mt = 0; mt < 4; mt++)
        aoff[mt] = (uint32_t)((m_base + mt * 16 + (quad & 1) * 8 + id8) * RSTR + ((quad >> 1) * 8) * 2);
#pragma unroll
    for (int np = 0; np < 2; np++)
        boff[np] = (uint32_t)((n_base + np * 16 + (quad >> 1) * 8 + id8) * RSTR + ((quad & 1) * 8) * 2);

    float d[4][4][4];
#pragma unroll
    for (int mt = 0; mt < 4; mt++)
#pragma unroll
        for (int nt = 0; nt < 4; nt++)
#pragma unroll
            for (int k = 0; k < 4; k++) d[mt][nt][k] = 0.f;

    const int nk = K / BK;

    load_tile(sb + 0 * TILEB, p0, K, 0);
    load_tile(sb + 1 * TILEB, p1, K, 0);
    load_tile(sb + 2 * TILEB, p2, K, 0);
    CP_COMMIT();
    if (nk > 1) {
        load_tile(sb + STG3 + 0 * TILEB, p0, K, BK);
        load_tile(sb + STG3 + 1 * TILEB, p1, K, BK);
        load_tile(sb + STG3 + 2 * TILEB, p2, K, BK);
        CP_COMMIT();
    }

    for (int i = 0; i < nk; i++) {
        if (i + 1 < nk) CP_WAIT1(); else CP_WAIT0();
        __syncthreads();
        const uint32_t st = sb + (i & 1) * STG3;

        if (SPLITB) { MMA_STAGE_SB(st); } else { MMA_STAGE_SA(st); }

        __syncthreads();
        if (i + 2 < nk) {
            const uint32_t nstg = sb + (i & 1) * STG3;
            const int k0 = (i + 2) * BK;
            load_tile(nstg + 0 * TILEB, p0, K, k0);
            load_tile(nstg + 1 * TILEB, p1, K, k0);
            load_tile(nstg + 2 * TILEB, p2, K, k0);
            CP_COMMIT();
        }
    }

    const int g = lane >> 2, t2 = (lane & 3) * 2;

    if (w1f) {
        // fused BN-stat + pool epilogue (GEMM3)
        float* red = (float*)dsm;
        const int nw = wid & 3;
#pragma unroll
        for (int mt = 0; mt < 4; mt++) {
            float s0r = 0, ss0 = 0, dt0 = 0, s1r = 0, ss1 = 0, dt1 = 0;
#pragma unroll
            for (int nt = 0; nt < 4; nt++) {
                const int col = n_base + nt * 8 + t2;
                float wa = __ldg(w1f + col), wb = __ldg(w1f + col + 1);
                float v00 = d[mt][nt][0], v01 = d[mt][nt][1];
                float v10 = d[mt][nt][2], v11 = d[mt][nt][3];
                s0r += v00 + v01;  ss0 = fmaf(v00, v00, fmaf(v01, v01, ss0));
                dt0 = fmaf(v00, wa, fmaf(v01, wb, dt0));
                s1r += v10 + v11;  ss1 = fmaf(v10, v10, fmaf(v11, v11, ss1));
                dt1 = fmaf(v10, wa, fmaf(v11, wb, dt1));
            }
#pragma unroll
            for (int o = 2; o > 0; o >>= 1) {
                s0r += __shfl_down_sync(0xffffffffu, s0r, o, 4);
                ss0 += __shfl_down_sync(0xffffffffu, ss0, o, 4);
                dt0 += __shfl_down_sync(0xffffffffu, dt0, o, 4);
                s1r += __shfl_down_sync(0xffffffffu, s1r, o, 4);
                ss1 += __shfl_down_sync(0xffffffffu, ss1, o, 4);
                dt1 += __shfl_down_sync(0xffffffffu, dt1, o, 4);
            }
            if ((lane & 3) == 0) {
                const int r0 = m_base + mt * 16 + g, r1 = r0 + 8;
                red[0 * 512 + nw * 128 + r0] = s0r; red[0 * 512 + nw * 128 + r1] = s1r;
                red[1 * 512 + nw * 128 + r0] = ss0; red[1 * 512 + nw * 128 + r1] = ss1;
                red[2 * 512 + nw * 128 + r0] = dt0; red[2 * 512 + nw * 128 + r1] = dt1;
            }
        }
        __syncthreads();
        if (tid < 128) {
            float s  = red[tid] + red[128 + tid] + red[256 + tid] + red[384 + tid];
            float ss = red[512 + tid] + red[640 + tid] + red[768 + tid] + red[896 + tid];
            float dt = red[1024 + tid] + red[1152 + tid] + red[1280 + tid] + red[1408 + tid];
            const size_t o = (size_t)bz * PS + Aoff + tid;
            sbc[o] = s; ssbc[o] = ss; dotb[o] = dt;
        }
        return;
    }

    // fp16 epilogue (GEMM2)
#pragma unroll
    for (int mt = 0; mt < 4; mt++) {
        const int r0 = m_base + mt * 16 + g;
        const int r1 = r0 + 8;
        const float bv0 = bias ? bias[Aoff + r0] : 0.f;
        const float bv1 = bias ? bias[Aoff + r1] : 0.f;
        const size_t base0 = (size_t)bz * o_bstr + (size_t)(Aoff + r0) * o_rstr;
        const size_t base1 = (size_t)bz * o_bstr + (size_t)(Aoff + r1) * o_rstr;
#pragma unroll
        for (int nt = 0; nt < 4; nt++) {
            const int col = n_base + nt * 8 + t2;
            *(__half2*)(oh + base0 + col) = __floats2half2_rn(d[mt][nt][0] + bv0, d[mt][nt][1] + bv0);
            *(__half2*)(oh + base1 + col) = __floats2half2_rn(d[mt][nt][2] + bv1, d[mt][nt][3] + bv1);
        }
    }
}

// ---------------------------------------------------------------------------
// small kernels
// ---------------------------------------------------------------------------
__global__ void k_wmeans(const float* __restrict__ wq, const float* __restrict__ wk,
                         const float* __restrict__ bq, const float* __restrict__ bk) {
    const int bx = blockIdx.x;
    if (bx < 48) {
        const int tx = threadIdx.x & 31, ty = threadIdx.x >> 5;
        const int c = bx * 32 + tx;
        float sq = 0.f, sk = 0.f;
        for (int o = ty; o < QK; o += 8) {
            sq += wq[(size_t)o * PS + c];
            sk += wk[(size_t)o * PS + c];
        }
        __shared__ float aq[8][32], ak[8][32];
        aq[ty][tx] = sq; ak[ty][tx] = sk;
        __syncthreads();
        if (ty == 0) {
#pragma unroll
            for (int u = 1; u < 8; u++) { sq += aq[u][tx]; sk += ak[u][tx]; }
            g_wqm[c] = sq * (1.0f / QK);
            g_wkm[c] = sk * (1.0f / QK);
        }
    } else if (threadIdx.x < 32) {
        const float* src = (bx == 48) ? bq : bk;
        float s = 0.f;
        for (int o = threadIdx.x; o < QK; o += 32) s += src[o];
#pragma unroll
        for (int o = 16; o > 0; o >>= 1) s += __shfl_down_sync(0xffffffffu, s, o);
        if (threadIdx.x == 0) g_bqkm[bx - 48] = s * (1.0f / QK);
    }
}

// q1/k1 from hs1^T (fp16), one warp per (b, j)
__global__ void k_qk() {
    const int wid = threadIdx.x >> 5, lane = threadIdx.x & 31;
    const int gw = blockIdx.x * 8 + wid;
    const int b = gw >> 7, j = gw & 127;
    const __half* h = g_h1 + (size_t)(b * NJ + j) * PS;
    float q = 0.f, k = 0.f;
    for (int c = lane * 2; c < PS; c += 64) {
        __half2 hv = *(const __half2*)(h + c);
        float2 v = __half22float2(hv);
        q = fmaf(g_wqm[c], v.x, q);
        k = fmaf(g_wkm[c], v.x, k);
        q = fmaf(g_wqm[c + 1], v.y, q);
        k = fmaf(g_wkm[c + 1], v.y, k);
    }
#pragma unroll
    for (int o = 16; o > 0; o >>= 1) {
        q += __shfl_down_sync(0xffffffffu, q, o);
        k += __shfl_down_sync(0xffffffffu, k, o);
    }
    if (lane == 0) {
        g_q1[b * NJ + j] = q + g_bqkm[0];
        g_k1[b * NJ + j] = k + g_bqkm[1];
    }
}

__global__ void k_A1t(const float* __restrict__ adj, const float* __restrict__ alpha) {
    const int b = blockIdx.y;
    const int idx = blockIdx.x * 256 + threadIdx.x;
    const int k = idx >> 7, j = idx & 127;
    float v = adj[j * NJ + k] + tanhf(g_q1[b * NJ + j] - g_k1[b * NJ + k]) * alpha[0];
    __half h = __float2half_rn(v);
    __half l = __float2half_rn(v - __half2float(h));
    g_a1hi[(size_t)b * NJ * NJ + idx] = h;
    g_a1lo[(size_t)b * NJ * NJ + idx] = l;
}

__global__ void k_hs4(const float* __restrict__ gamma, const float* __restrict__ beta,
                      const float* __restrict__ w1, const float* __restrict__ b1) {
    const int c = blockIdx.x * 256 + threadIdx.x;
    float sw = 0.f;
#pragma unroll 16
    for (int j = 0; j < NJ; j++) sw += w1[j];
    float s = 0.f, ss = 0.f;
    for (int b = 0; b < BB; b++) {
        s  += g_sbc [b * PS + c];
        ss += g_ssbc[b * PS + c];
    }
    const float inv = 1.0f / (BB * NJ);
    float mean = s * inv;
    float var = ss * inv - mean * mean;
    float rstd = rsqrtf(var + 1e-5f);
    float ga = gamma[c] * rstd;
    float be = beta[c] * sw + b1[0];
    float msw = mean * sw;
    for (int b = 0; b < BB; b++)
        g_hs4[b * PS + c] = ga * (g_dotb[b * PS + c] - msw) + be;
}

__global__ void k_cls(const float* __restrict__ wcls, const float* __restrict__ bcls,
                      float* __restrict__ out) {
    __shared__ __align__(16) float sh[PS];
    const int b = blockIdx.x;
    for (int i = threadIdx.x; i < PS; i += blockDim.x) sh[i] = g_hs4[b * PS + i];
    __syncthreads();
    const int n = threadIdx.x;
    if (n < NC) {
        float acc = bcls[n];
        const float4* w4 = (const float4*)(wcls + (size_t)n * PS);
        const float4* s4 = (const float4*)sh;
        for (int c = 0; c < PS / 4; c++) {
            float4 w = w4[c], s = s4[c];
            acc = fmaf(s.x, w.x, acc);
            acc = fmaf(s.y, w.y, acc);
            acc = fmaf(s.z, w.z, acc);
            acc = fmaf(s.w, w.w, acc);
        }
        out[b * NC + n] = acc;
    }
}

// ---------------------------------------------------------------------------
// launch
// ---------------------------------------------------------------------------
extern "C" void kernel_launch(void* const* d_in, const int* in_sizes, int n_in,
                              void* d_out, int out_size) {
    (void)in_sizes; (void)n_in; (void)out_size;
    const float* x       = (const float*)d_in[0];
    const float* w_pool0 = (const float*)d_in[1];
    const float* b_pool0 = (const float*)d_in[2];
    const float* adj1    = (const float*)d_in[3];
    const float* w_q     = (const float*)d_in[4];
    const float* b_q     = (const float*)d_in[5];
    const float* w_k     = (const float*)d_in[6];
    const float* b_k     = (const float*)d_in[7];
    const float* alpha   = (const float*)d_in[8];
    const float* w_c1    = (const float*)d_in[9];
    const float* b_c1    = (const float*)d_in[10];
    const float* gamma   = (const float*)d_in[11];
    const float* beta    = (const float*)d_in[12];
    const float* w_pool1 = (const float*)d_in[13];
    const float* b_pool1 = (const float*)d_in[14];
    const float* w_cls   = (const float*)d_in[15];
    const float* b_cls   = (const float*)d_in[16];
    float* out = (float*)d_out;

    __half *w0hi, *w0lo, *c1hi, *c1lo, *h1, *h2, *a1hi, *a1lo;
    float *sbc, *ssbc, *dotb;
    cudaGetSymbolAddress((void**)&w0hi, g_w0hi);
    cudaGetSymbolAddress((void**)&w0lo, g_w0lo);
    cudaGetSymbolAddress((void**)&c1hi, g_c1hi);
    cudaGetSymbolAddress((void**)&c1lo, g_c1lo);
    cudaGetSymbolAddress((void**)&h1,   g_h1);
    cudaGetSymbolAddress((void**)&h2,   g_h2);
    cudaGetSymbolAddress((void**)&a1hi, g_a1hi);
    cudaGetSymbolAddress((void**)&a1lo, g_a1lo);
    cudaGetSymbolAddress((void**)&sbc,  g_sbc);
    cudaGetSymbolAddress((void**)&ssbc, g_ssbc);
    cudaGetSymbolAddress((void**)&dotb, g_dotb);

    const int smem_bytes = 2 * STG3;   // 208896
    cudaFuncSetAttribute(mma_gemm<0>, cudaFuncAttributeMaxDynamicSharedMemorySize, smem_bytes);
    cudaFuncSetAttribute(mma_gemm<1>, cudaFuncAttributeMaxDynamicSharedMemorySize, smem_bytes);
    cudaFuncSetAttribute(mma_gemm_x, cudaFuncAttributeMaxDynamicSharedMemorySize, smem_bytes);

    // weight hi/lo splits (small)
    {
        long n4 = (long)NJ * TNS / 4;
        k_cvt<<<(unsigned)((n4 + 255) / 256), 256>>>(w_pool0, w0hi, w0lo, n4);
        n4 = (long)PS * PS / 4;
        k_cvt<<<(unsigned)((n4 + 255) / 256), 256>>>(w_c1, c1hi, c1lo, n4);
    }
    k_wmeans<<<50, 256>>>(w_q, w_k, b_q, b_k);

    // GEMM1: hs1^T[b][j][c] = (w0h+w0l)[j,:] . x[b][c,:] + b_pool0[j]
    mma_gemm_x<<<dim3(12, 1, BB), 256, smem_bytes>>>(
        w0hi, w0lo,
        x, (long)PS * TNS,
        TNS, b_pool0,
        h1, (long)NJ * PS, PS);

    k_qk<<<512, 256>>>();
    k_A1t<<<dim3(64, BB), 256>>>(adj1, alpha);

    // GEMM2: hs2[b][o][j] = (c1h+c1l)[o,:] . hs1^T[b][j,:] + b_c1[o]
    mma_gemm<0><<<dim3(12, 1, BB), 256, smem_bytes>>>(
        c1hi, 0L, c1lo, 0L,
        h1, (long)NJ * PS,
        PS, b_c1,
        h2, (long)PS * NJ, NJ,
        nullptr, nullptr, nullptr, nullptr);

    // GEMM3 (fused BN stats + pool): hs3[b][c][k] = hs2[b][c,:] . (a1h+a1l)^T[b][k,:]
    mma_gemm<1><<<dim3(12, 1, BB), 256, smem_bytes>>>(
        h2, (long)PS * NJ,
        a1hi, (long)NJ * NJ,
        a1lo, (long)NJ * NJ,
        NJ, nullptr,
        nullptr, 0L, 0,
        w_pool1, sbc, ssbc, dotb);

    k_hs4<<<PS / 256, 256>>>(gamma, beta, w_pool1, b_pool1);
    k_cls<<<BB, 256>>>(w_cls, b_cls, out);
}

// round 10
// speedup vs baseline: 1.1367x; 1.1367x over previous
#include <cuda_runtime.h>
#include <cuda_fp16.h>
#include <cstdint>
#include <cstddef>

#define BB   32
#define PS   1536
#define TNS  2048
#define NJ   128
#define QK   384
#define NC   200

// ---------------------------------------------------------------------------
// scratch (static device globals; no allocation)
// ---------------------------------------------------------------------------
__device__ __half g_w0hi[(size_t)NJ * TNS];
__device__ __half g_w0lo[(size_t)NJ * TNS];
__device__ __half g_c1hi[(size_t)PS * PS];
__device__ __half g_c1lo[(size_t)PS * PS];
__device__ __half g_h1  [(size_t)BB * NJ * PS];   // hs1^T [b][j][c], fp16
__device__ __half g_a1hi[(size_t)BB * NJ * NJ];   // A1^T  [b][k][j]
__device__ __half g_a1lo[(size_t)BB * NJ * NJ];
__device__ float g_sbc [(size_t)BB * PS];
__device__ float g_ssbc[(size_t)BB * PS];
__device__ float g_dotb[(size_t)BB * PS];
__device__ float g_q1 [BB * NJ];
__device__ float g_k1 [BB * NJ];
__device__ float g_wqm[PS];
__device__ float g_wkm[PS];
__device__ float g_bqkm[2];
__device__ float g_hs4[BB * PS];

// ---------------------------------------------------------------------------
// helpers
// ---------------------------------------------------------------------------
__device__ __forceinline__ uint32_t smem_u32(const void* p) {
    uint32_t a;
    asm("{ .reg .u64 t; cvta.to.shared.u64 t, %1; cvt.u32.u64 %0, t; }" : "=r"(a) : "l"(p));
    return a;
}
#define CP_COMMIT() asm volatile("cp.async.commit_group;" ::: "memory")
#define CP_WAIT0()  asm volatile("cp.async.wait_group 0;" ::: "memory")
#define CP_WAIT1()  asm volatile("cp.async.wait_group 1;" ::: "memory")

__device__ __forceinline__ void ld4(uint32_t* r, uint32_t a) {
    asm volatile("ldmatrix.sync.aligned.m8n8.x4.shared.b16 {%0,%1,%2,%3}, [%4];"
        : "=r"(r[0]), "=r"(r[1]), "=r"(r[2]), "=r"(r[3]) : "r"(a));
}
__device__ __forceinline__ void mma16816(float* d, const uint32_t* a, const uint32_t* b) {
    asm volatile(
        "mma.sync.aligned.m16n8k16.row.col.f32.f16.f16.f32 "
        "{%0,%1,%2,%3}, {%4,%5,%6,%7}, {%8,%9}, {%0,%1,%2,%3};"
        : "+f"(d[0]), "+f"(d[1]), "+f"(d[2]), "+f"(d[3])
        : "r"(a[0]), "r"(a[1]), "r"(a[2]), "r"(a[3]), "r"(b[0]), "r"(b[1]));
}

// fp32 -> (hi, lo) fp16 split (standalone pass for weights)
__global__ void k_cvt(const float* __restrict__ s, __half* __restrict__ hi,
                      __half* __restrict__ lo, long n4) {
    long i = (long)blockIdx.x * blockDim.x + threadIdx.x;
    if (i >= n4) return;
    float4 v = ((const float4*)s)[i];
    __half h0 = __float2half_rn(v.x), h1 = __float2half_rn(v.y);
    __half h2 = __float2half_rn(v.z), h3 = __float2half_rn(v.w);
    __half l0 = __float2half_rn(v.x - __half2float(h0));
    __half l1 = __float2half_rn(v.y - __half2float(h1));
    __half l2 = __float2half_rn(v.z - __half2float(h2));
    __half l3 = __float2half_rn(v.w - __half2float(h3));
    __half2 ph0; ph0.x = h0; ph0.y = h1;
    __half2 ph1; ph1.x = h2; ph1.y = h3;
    __half2 pl0; pl0.x = l0; pl0.y = l1;
    __half2 pl1; pl1.x = l2; pl1.y = l3;
    ((__half2*)hi)[i * 2 + 0] = ph0;
    ((__half2*)hi)[i * 2 + 1] = ph1;
    ((__half2*)lo)[i * 2 + 0] = pl0;
    ((__half2*)lo)[i * 2 + 1] = pl1;
}

// ---------------------------------------------------------------------------
// SMEM tile layout: 2 stages x 3 tiles, 128 rows x 64 k (fp16, 128B/row + 16 pad)
// ---------------------------------------------------------------------------
#define BK    64
#define RSTR  144
#define TILEB (128 * RSTR)     // 18432
#define STG3  (3 * TILEB)      // 55296

__device__ __forceinline__ void load_tile(uint32_t sb, const __half* g, int gstride, int k0) {
    const int t = threadIdx.x;
#pragma unroll
    for (int p = 0; p < 4; p++) {
        int idx = p * 256 + t;
        int row = idx >> 3, ch = idx & 7;
        uint32_t dst = sb + row * RSTR + ch * 16;
        const void* src = g + (size_t)row * gstride + k0 + ch * 8;
        asm volatile("cp.async.cg.shared.global [%0], [%1], 16;" :: "r"(dst), "l"(src));
    }
}

// 2-term MMA over one stage (4 k16 steps), split-A: tile0=Ah, tile1=Al, tile2=B
#define MMA_STAGE_SA(st)                                                         \
    do {                                                                         \
        _Pragma("unroll")                                                        \
        for (int ks = 0; ks < 4; ks++) {                                         \
            const uint32_t klo = ks * 32;                                        \
            uint32_t ah[4][4], bf[2][4];                                         \
            _Pragma("unroll")                                                    \
            for (int mt = 0; mt < 4; mt++) ld4(ah[mt], (st) + 0 * TILEB + aoff[mt] + klo); \
            _Pragma("unroll")                                                    \
            for (int np = 0; np < 2; np++) ld4(bf[np], (st) + 2 * TILEB + boff[np] + klo); \
            _Pragma("unroll")                                                    \
            for (int mt = 0; mt < 4; mt++)                                       \
                _Pragma("unroll")                                                \
                for (int nt = 0; nt < 4; nt++)                                   \
                    mma16816(d[mt][nt], ah[mt], &bf[nt >> 1][(nt & 1) * 2]);     \
            {                                                                    \
                uint32_t al[4][4];                                               \
                _Pragma("unroll")                                                \
                for (int mt = 0; mt < 4; mt++) ld4(al[mt], (st) + 1 * TILEB + aoff[mt] + klo); \
                _Pragma("unroll")                                                \
                for (int mt = 0; mt < 4; mt++)                                   \
                    _Pragma("unroll")                                            \
                    for (int nt = 0; nt < 4; nt++)                               \
                        mma16816(d[mt][nt], al[mt], &bf[nt >> 1][(nt & 1) * 2]); \
            }                                                                    \
        }                                                                        \
    } while (0)

// 2-term MMA over one 64-k chunk, explicit slots: A single, B hi/lo
#define MMA_STAGE_SB3(sA, sBh, sBl)                                              \
    do {                                                                         \
        _Pragma("unroll")                                                        \
        for (int ks = 0; ks < 4; ks++) {                                         \
            const uint32_t klo = ks * 32;                                        \
            uint32_t af[4][4], bh[2][4];                                         \
            _Pragma("unroll")                                                    \
            for (int mt = 0; mt < 4; mt++) ld4(af[mt], (sA) + aoff[mt] + klo);   \
            _Pragma("unroll")                                                    \
            for (int np = 0; np < 2; np++) ld4(bh[np], (sBh) + boff[np] + klo);  \
            _Pragma("unroll")                                                    \
            for (int mt = 0; mt < 4; mt++)                                       \
                _Pragma("unroll")                                                \
                for (int nt = 0; nt < 4; nt++)                                   \
                    mma16816(d[mt][nt], af[mt], &bh[nt >> 1][(nt & 1) * 2]);     \
            {                                                                    \
                uint32_t bl[2][4];                                               \
                _Pragma("unroll")                                                \
                for (int np = 0; np < 2; np++) ld4(bl[np], (sBl) + boff[np] + klo); \
                _Pragma("unroll")                                                \
                for (int mt = 0; mt < 4; mt++)                                   \
                    _Pragma("unroll")                                            \
                    for (int nt = 0; nt < 4; nt++)                               \
                        mma16816(d[mt][nt], af[mt], &bl[nt >> 1][(nt & 1) * 2]); \
            }                                                                    \
        }                                                                        \
    } while (0)

// ---------------------------------------------------------------------------
// GEMM1: D[j, c-tile] = (w0h + w0l)[j,:] . x_fp16[b, c,:]  -> hs1^T fp16
// ---------------------------------------------------------------------------
__device__ __forceinline__ void ldgB(float4* br, const float* pB, int K, int k0) {
    const int t = threadIdx.x;
#pragma unroll
    for (int p = 0; p < 8; p++) {
        int idx = p * 256 + t;
        int row = idx >> 4, f4 = idx & 15;
        br[p] = *(const float4*)(pB + (size_t)row * K + k0 + f4 * 4);
    }
}
__device__ __forceinline__ void cvt_sts(const float4* br, uint32_t st) {
    const int t = threadIdx.x;
#pragma unroll
    for (int p = 0; p < 8; p++) {
        int idx = p * 256 + t;
        int row = idx >> 4, f4 = idx & 15;
        float4 v = br[p];
        __half2 h01 = __floats2half2_rn(v.x, v.y);
        __half2 h23 = __floats2half2_rn(v.z, v.w);
        uint32_t off = (uint32_t)(row * RSTR + f4 * 8);
        asm volatile("st.shared.v2.b32 [%0], {%1,%2};"
            :: "r"(st + 2 * TILEB + off), "r"(*(uint32_t*)&h01), "r"(*(uint32_t*)&h23));
    }
}

__global__ __launch_bounds__(256, 1) void mma_gemm_x(
    const __half* __restrict__ Ah, const __half* __restrict__ Al,
    const float* __restrict__ Bf, long b_bstr,
    int K,
    const float* __restrict__ bias,
    __half* __restrict__ oh,
    long o_bstr, int o_rstr)
{
    extern __shared__ char dsm[];
    const uint32_t sb = smem_u32(dsm);

    const int tid = threadIdx.x;
    const int wid = tid >> 5, lane = tid & 31;
    const int bz = blockIdx.z;
    const int Boff = blockIdx.x * 128;
    const float* pBf = Bf + (size_t)bz * b_bstr + (size_t)Boff * K;

    const int m_base = (wid >> 2) * 64;
    const int n_base = (wid & 3) * 32;
    const int quad = lane >> 3, id8 = lane & 7;

    uint32_t aoff[4], boff[2];
#pragma unroll
    for (int mt = 0; mt < 4; mt++)
        aoff[mt] = (uint32_t)((m_base + mt * 16 + (quad & 1) * 8 + id8) * RSTR + ((quad >> 1) * 8) * 2);
#pragma unroll
    for (int np = 0; np < 2; np++)
        boff[np] = (uint32_t)((n_base + np * 16 + (quad >> 1) * 8 + id8) * RSTR + ((quad & 1) * 8) * 2);

    float d[4][4][4];
#pragma unroll
    for (int mt = 0; mt < 4; mt++)
#pragma unroll
        for (int nt = 0; nt < 4; nt++)
#pragma unroll
            for (int k = 0; k < 4; k++) d[mt][nt][k] = 0.f;

    const int nk = K / BK;
    float4 breg[8];

    // prologue: chunk0 + chunk1 staged
    ldgB(breg, pBf, K, 0);
    cvt_sts(breg, sb);
    load_tile(sb + 0 * TILEB, Ah, K, 0);
    load_tile(sb + 1 * TILEB, Al, K, 0);
    CP_COMMIT();
    ldgB(breg, pBf, K, BK);
    cvt_sts(breg, sb + STG3);
    load_tile(sb + STG3 + 0 * TILEB, Ah, K, BK);
    load_tile(sb + STG3 + 1 * TILEB, Al, K, BK);
    CP_COMMIT();
    CP_WAIT1();
    __syncthreads();

    for (int i = 0; i < nk; i++) {
        const uint32_t st = sb + (i & 1) * STG3;
        if (i + 2 < nk) ldgB(breg, pBf, K, (i + 2) * BK);

        MMA_STAGE_SA(st);

        __syncthreads();                      // stage (i&1) free
        if (i + 2 < nk) {
            cvt_sts(breg, st);
            load_tile(st + 0 * TILEB, Ah, K, (i + 2) * BK);
            load_tile(st + 1 * TILEB, Al, K, (i + 2) * BK);
            CP_COMMIT();
        }
        if (i + 1 < nk) {
            if (i + 2 < nk) CP_WAIT1(); else CP_WAIT0();
            __syncthreads();                  // stage (i+1) ready
        }
    }

    // epilogue: fp16 single
    const int g = lane >> 2, t2 = (lane & 3) * 2;
#pragma unroll
    for (int mt = 0; mt < 4; mt++) {
        const int r0 = m_base + mt * 16 + g;
        const int r1 = r0 + 8;
        const float bv0 = bias ? bias[r0] : 0.f;
        const float bv1 = bias ? bias[r1] : 0.f;
        const size_t base0 = (size_t)bz * o_bstr + (size_t)r0 * o_rstr + Boff;
        const size_t base1 = (size_t)bz * o_bstr + (size_t)r1 * o_rstr + Boff;
#pragma unroll
        for (int nt = 0; nt < 4; nt++) {
            const int col = n_base + nt * 8 + t2;
            *(__half2*)(oh + base0 + col) = __floats2half2_rn(d[mt][nt][0] + bv0, d[mt][nt][1] + bv0);
            *(__half2*)(oh + base1 + col) = __floats2half2_rn(d[mt][nt][2] + bv1, d[mt][nt][3] + bv1);
        }
    }
}

// ---------------------------------------------------------------------------
// GEMM2 + fused GEMM3 + fused BN-stat/pool:
//   hs2-tile[o 128, j 128] = (c1h+c1l)[o,:] . h1^T[b][j,:] + b_c1[o]   (mainloop)
//   then in-SMEM:  hs3-tile[o, k 128] = hs2-tile . (a1h+a1l)[b][k][j]
//   then per (b, o): sum_k, sum_k^2, dot(w_pool1) reductions -> global.
// ---------------------------------------------------------------------------
__global__ __launch_bounds__(256, 1) void mma_gemm2f(
    const __half* __restrict__ C1h, const __half* __restrict__ C1l,
    const __half* __restrict__ H1, long h1_bstr,
    const __half* __restrict__ A1h, const __half* __restrict__ A1l,
    int K,
    const float* __restrict__ bias,
    const float* __restrict__ w1f,
    float* __restrict__ sbc, float* __restrict__ ssbc, float* __restrict__ dotb)
{
    extern __shared__ char dsm[];
    const uint32_t sb = smem_u32(dsm);

    const int tid = threadIdx.x;
    const int wid = tid >> 5, lane = tid & 31;
    const int bz = blockIdx.z;
    const int Aoff = blockIdx.x * 128;

    const __half* p0 = C1h + (size_t)Aoff * K;
    const __half* p1 = C1l + (size_t)Aoff * K;
    const __half* p2 = H1 + (size_t)bz * h1_bstr;
    const __half* a1h_b = A1h + (size_t)bz * NJ * NJ;
    const __half* a1l_b = A1l + (size_t)bz * NJ * NJ;

    const int m_base = (wid >> 2) * 64;
    const int n_base = (wid & 3) * 32;
    const int quad = lane >> 3, id8 = lane & 7;

    uint32_t aoff[4], boff[2];
#pragma unroll
    for (int mt = 0; mt < 4; mt++)
        aoff[mt] = (uint32_t)((m_base + mt * 16 + (quad & 1) * 8 + id8) * RSTR + ((quad >> 1) * 8) * 2);
#pragma unroll
    for (int np = 0; np < 2; np++)
        boff[np] = (uint32_t)((n_base + np * 16 + (quad >> 1) * 8 + id8) * RSTR + ((quad & 1) * 8) * 2);

    float d[4][4][4];
#pragma unroll
    for (int mt = 0; mt < 4; mt++)
#pragma unroll
        for (int nt = 0; nt < 4; nt++)
#pragma unroll
            for (int k = 0; k < 4; k++) d[mt][nt][k] = 0.f;

    const int nk = K / BK;

    load_tile(sb + 0 * TILEB, p0, K, 0);
    load_tile(sb + 1 * TILEB, p1, K, 0);
    load_tile(sb + 2 * TILEB, p2, K, 0);
    CP_COMMIT();
    load_tile(sb + STG3 + 0 * TILEB, p0, K, BK);
    load_tile(sb + STG3 + 1 * TILEB, p1, K, BK);
    load_tile(sb + STG3 + 2 * TILEB, p2, K, BK);
    CP_COMMIT();

    for (int i = 0; i < nk; i++) {
        if (i + 1 < nk) CP_WAIT1(); else CP_WAIT0();
        __syncthreads();
        const uint32_t st = sb + (i & 1) * STG3;

        MMA_STAGE_SA(st);

        __syncthreads();
        if (i + 2 < nk) {
            const uint32_t nstg = sb + (i & 1) * STG3;
            const int k0 = (i + 2) * BK;
            load_tile(nstg + 0 * TILEB, p0, K, k0);
            load_tile(nstg + 1 * TILEB, p1, K, k0);
            load_tile(nstg + 2 * TILEB, p2, K, k0);
            CP_COMMIT();
        }
    }
    // after loop: all stages free (last MMA done, post-sync)

    // --- fused GEMM3 prologue: preload A1 hi/lo tiles into free slots ---
    // slots: A0=sb+0, A1=sb+1T, Bh0=sb+2T, Bl0=sb+3T, Bh1=sb+4T, Bl1=sb+5T
    load_tile(sb + 2 * TILEB, a1h_b, NJ, 0);
    load_tile(sb + 3 * TILEB, a1l_b, NJ, 0);
    load_tile(sb + 4 * TILEB, a1h_b, NJ, 64);
    load_tile(sb + 5 * TILEB, a1l_b, NJ, 64);
    CP_COMMIT();

    // write hs2 tile (+bias, fp16) into A slots, j split across 2 slots
    const int g = lane >> 2, t2 = (lane & 3) * 2;
#pragma unroll
    for (int mt = 0; mt < 4; mt++) {
        const int r0 = m_base + mt * 16 + g;
        const int r1 = r0 + 8;
        const float bv0 = bias[Aoff + r0];
        const float bv1 = bias[Aoff + r1];
#pragma unroll
        for (int nt = 0; nt < 4; nt++) {
            const int col = n_base + nt * 8 + t2;
            const uint32_t cslot = (uint32_t)(col >> 6) * TILEB;
            const uint32_t cl = (uint32_t)(col & 63) * 2;
            __half2 v0 = __floats2half2_rn(d[mt][nt][0] + bv0, d[mt][nt][1] + bv0);
            __half2 v1 = __floats2half2_rn(d[mt][nt][2] + bv1, d[mt][nt][3] + bv1);
            asm volatile("st.shared.b32 [%0], %1;"
                :: "r"(sb + cslot + (uint32_t)r0 * RSTR + cl), "r"(*(uint32_t*)&v0));
            asm volatile("st.shared.b32 [%0], %1;"
                :: "r"(sb + cslot + (uint32_t)r1 * RSTR + cl), "r"(*(uint32_t*)&v1));
        }
    }
    CP_WAIT0();
    __syncthreads();

    // zero accumulators, run the two 64-k GEMM3 chunks
#pragma unroll
    for (int mt = 0; mt < 4; mt++)
#pragma unroll
        for (int nt = 0; nt < 4; nt++)
#pragma unroll
            for (int k = 0; k < 4; k++) d[mt][nt][k] = 0.f;

    MMA_STAGE_SB3(sb + 0 * TILEB, sb + 2 * TILEB, sb + 3 * TILEB);
    MMA_STAGE_SB3(sb + 1 * TILEB, sb + 4 * TILEB, sb + 5 * TILEB);

    // --- fused BN-stat + pool epilogue ---
    __syncthreads();
    float* red = (float*)dsm;
    const int nw = wid & 3;
#pragma unroll
    for (int mt = 0; mt < 4; mt++) {
        float s0r = 0, ss0 = 0, dt0 = 0, s1r = 0, ss1 = 0, dt1 = 0;
#pragma unroll
        for (int nt = 0; nt < 4; nt++) {
            const int col = n_base + nt * 8 + t2;
            float wa = __ldg(w1f + col), wb = __ldg(w1f + col + 1);
            float v00 = d[mt][nt][0], v01 = d[mt][nt][1];
            float v10 = d[mt][nt][2], v11 = d[mt][nt][3];
            s0r += v00 + v01;  ss0 = fmaf(v00, v00, fmaf(v01, v01, ss0));
            dt0 = fmaf(v00, wa, fmaf(v01, wb, dt0));
            s1r += v10 + v11;  ss1 = fmaf(v10, v10, fmaf(v11, v11, ss1));
            dt1 = fmaf(v10, wa, fmaf(v11, wb, dt1));
        }
#pragma unroll
        for (int o = 2; o > 0; o >>= 1) {
            s0r += __shfl_down_sync(0xffffffffu, s0r, o, 4);
            ss0 += __shfl_down_sync(0xffffffffu, ss0, o, 4);
            dt0 += __shfl_down_sync(0xffffffffu, dt0, o, 4);
            s1r += __shfl_down_sync(0xffffffffu, s1r, o, 4);
            ss1 += __shfl_down_sync(0xffffffffu, ss1, o, 4);
            dt1 += __shfl_down_sync(0xffffffffu, dt1, o, 4);
        }
        if ((lane & 3) == 0) {
            const int r0 = m_base + mt * 16 + g, r1 = r0 + 8;
            red[0 * 512 + nw * 128 + r0] = s0r; red[0 * 512 + nw * 128 + r1] = s1r;
            red[1 * 512 + nw * 128 + r0] = ss0; red[1 * 512 + nw * 128 + r1] = ss1;
            red[2 * 512 + nw * 128 + r0] = dt0; red[2 * 512 + nw * 128 + r1] = dt1;
        }
    }
    __syncthreads();
    if (tid < 128) {
        float s  = red[tid] + red[128 + tid] + red[256 + tid] + red[384 + tid];
        float ss = red[512 + tid] + red[640 + tid] + red[768 + tid] + red[896 + tid];
        float dt = red[1024 + tid] + red[1152 + tid] + red[1280 + tid] + red[1408 + tid];
        const size_t o = (size_t)bz * PS + Aoff + tid;
        sbc[o] = s; ssbc[o] = ss; dotb[o] = dt;
    }
}

// ---------------------------------------------------------------------------
// small kernels
// ---------------------------------------------------------------------------
__global__ void k_wmeans(const float* __restrict__ wq, const float* __restrict__ wk,
                         const float* __restrict__ bq, const float* __restrict__ bk) {
    const int bx = blockIdx.x;
    if (bx < 48) {
        const int tx = threadIdx.x & 31, ty = threadIdx.x >> 5;
        const int c = bx * 32 + tx;
        float sq = 0.f, sk = 0.f;
        for (int o = ty; o < QK; o += 8) {
            sq += wq[(size_t)o * PS + c];
            sk += wk[(size_t)o * PS + c];
        }
        __shared__ float aq[8][32], ak[8][32];
        aq[ty][tx] = sq; ak[ty][tx] = sk;
        __syncthreads();
        if (ty == 0) {
#pragma unroll
            for (int u = 1; u < 8; u++) { sq += aq[u][tx]; sk += ak[u][tx]; }
            g_wqm[c] = sq * (1.0f / QK);
            g_wkm[c] = sk * (1.0f / QK);
        }
    } else if (threadIdx.x < 32) {
        const float* src = (bx == 48) ? bq : bk;
        float s = 0.f;
        for (int o = threadIdx.x; o < QK; o += 32) s += src[o];
#pragma unroll
        for (int o = 16; o > 0; o >>= 1) s += __shfl_down_sync(0xffffffffu, s, o);
        if (threadIdx.x == 0) g_bqkm[bx - 48] = s * (1.0f / QK);
    }
}

// q1/k1 from hs1^T (fp16), one warp per (b, j)
__global__ void k_qk() {
    const int wid = threadIdx.x >> 5, lane = threadIdx.x & 31;
    const int gw = blockIdx.x * 8 + wid;
    const int b = gw >> 7, j = gw & 127;
    const __half* h = g_h1 + (size_t)(b * NJ + j) * PS;
    float q = 0.f, k = 0.f;
    for (int c = lane * 2; c < PS; c += 64) {
        __half2 hv = *(const __half2*)(h + c);
        float2 v = __half22float2(hv);
        q = fmaf(g_wqm[c], v.x, q);
        k = fmaf(g_wkm[c], v.x, k);
        q = fmaf(g_wqm[c + 1], v.y, q);
        k = fmaf(g_wkm[c + 1], v.y, k);
    }
#pragma unroll
    for (int o = 16; o > 0; o >>= 1) {
        q += __shfl_down_sync(0xffffffffu, q, o);
        k += __shfl_down_sync(0xffffffffu, k, o);
    }
    if (lane == 0) {
        g_q1[b * NJ + j] = q + g_bqkm[0];
        g_k1[b * NJ + j] = k + g_bqkm[1];
    }
}

__global__ void k_A1t(const float* __restrict__ adj, const float* __restrict__ alpha) {
    const int b = blockIdx.y;
    const int idx = blockIdx.x * 256 + threadIdx.x;
    const int k = idx >> 7, j = idx & 127;
    float v = adj[j * NJ + k] + tanhf(g_q1[b * NJ + j] - g_k1[b * NJ + k]) * alpha[0];
    __half h = __float2half_rn(v);
    __half l = __float2half_rn(v - __half2float(h));
    g_a1hi[(size_t)b * NJ * NJ + idx] = h;
    g_a1lo[(size_t)b * NJ * NJ + idx] = l;
}

__global__ void k_hs4(const float* __restrict__ gamma, const float* __restrict__ beta,
                      const float* __restrict__ w1, const float* __restrict__ b1) {
    const int c = blockIdx.x * 256 + threadIdx.x;
    float sw = 0.f;
#pragma unroll 16
    for (int j = 0; j < NJ; j++) sw += w1[j];
    float s = 0.f, ss = 0.f;
    for (int b = 0; b < BB; b++) {
        s  += g_sbc [b * PS + c];
        ss += g_ssbc[b * PS + c];
    }
    const float inv = 1.0f / (BB * NJ);
    float mean = s * inv;
    float var = ss * inv - mean * mean;
    float rstd = rsqrtf(var + 1e-5f);
    float ga = gamma[c] * rstd;
    float be = beta[c] * sw + b1[0];
    float msw = mean * sw;
    for (int b = 0; b < BB; b++)
        g_hs4[b * PS + c] = ga * (g_dotb[b * PS + c] - msw) + be;
}

__global__ void k_cls(const float* __restrict__ wcls, const float* __restrict__ bcls,
                      float* __restrict__ out) {
    __shared__ __align__(16) float sh[PS];
    const int b = blockIdx.x;
    for (int i = threadIdx.x; i < PS; i += blockDim.x) sh[i] = g_hs4[b * PS + i];
    __syncthreads();
    const int n = threadIdx.x;
    if (n < NC) {
        float acc = bcls[n];
        const float4* w4 = (const float4*)(wcls + (size_t)n * PS);
        const float4* s4 = (const float4*)sh;
        for (int c = 0; c < PS / 4; c++) {
            float4 w = w4[c], s = s4[c];
            acc = fmaf(s.x, w.x, acc);
            acc = fmaf(s.y, w.y, acc);
            acc = fmaf(s.z, w.z, acc);
            acc = fmaf(s.w, w.w, acc);
        }
        out[b * NC + n] = acc;
    }
}

// ---------------------------------------------------------------------------
// launch
// ---------------------------------------------------------------------------
extern "C" void kernel_launch(void* const* d_in, const int* in_sizes, int n_in,
                              void* d_out, int out_size) {
    (void)in_sizes; (void)n_in; (void)out_size;
    const float* x       = (const float*)d_in[0];
    const float* w_pool0 = (const float*)d_in[1];
    const float* b_pool0 = (const float*)d_in[2];
    const float* adj1    = (const float*)d_in[3];
    const float* w_q     = (const float*)d_in[4];
    const float* b_q     = (const float*)d_in[5];
    const float* w_k     = (const float*)d_in[6];
    const float* b_k     = (const float*)d_in[7];
    const float* alpha   = (const float*)d_in[8];
    const float* w_c1    = (const float*)d_in[9];
    const float* b_c1    = (const float*)d_in[10];
    const float* gamma   = (const float*)d_in[11];
    const float* beta    = (const float*)d_in[12];
    const float* w_pool1 = (const float*)d_in[13];
    const float* b_pool1 = (const float*)d_in[14];
    const float* w_cls   = (const float*)d_in[15];
    const float* b_cls   = (const float*)d_in[16];
    float* out = (float*)d_out;

    __half *w0hi, *w0lo, *c1hi, *c1lo, *h1, *a1hi, *a1lo;
    float *sbc, *ssbc, *dotb;
    cudaGetSymbolAddress((void**)&w0hi, g_w0hi);
    cudaGetSymbolAddress((void**)&w0lo, g_w0lo);
    cudaGetSymbolAddress((void**)&c1hi, g_c1hi);
    cudaGetSymbolAddress((void**)&c1lo, g_c1lo);
    cudaGetSymbolAddress((void**)&h1,   g_h1);
    cudaGetSymbolAddress((void**)&a1hi, g_a1hi);
    cudaGetSymbolAddress((void**)&a1lo, g_a1lo);
    cudaGetSymbolAddress((void**)&sbc,  g_sbc);
    cudaGetSymbolAddress((void**)&ssbc, g_ssbc);
    cudaGetSymbolAddress((void**)&dotb, g_dotb);

    const int smem_bytes = 2 * STG3;   // 110592
    cudaFuncSetAttribute(mma_gemm2f, cudaFuncAttributeMaxDynamicSharedMemorySize, smem_bytes);
    cudaFuncSetAttribute(mma_gemm_x, cudaFuncAttributeMaxDynamicSharedMemorySize, smem_bytes);

    // weight hi/lo splits (small)
    {
        long n4 = (long)NJ * TNS / 4;
        k_cvt<<<(unsigned)((n4 + 255) / 256), 256>>>(w_pool0, w0hi, w0lo, n4);
        n4 = (long)PS * PS / 4;
        k_cvt<<<(unsigned)((n4 + 255) / 256), 256>>>(w_c1, c1hi, c1lo, n4);
    }
    k_wmeans<<<50, 256>>>(w_q, w_k, b_q, b_k);

    // GEMM1: hs1^T[b][j][c] = (w0h+w0l)[j,:] . x[b][c,:] + b_pool0[j]
    mma_gemm_x<<<dim3(12, 1, BB), 256, smem_bytes>>>(
        w0hi, w0lo,
        x, (long)PS * TNS,
        TNS, b_pool0,
        h1, (long)NJ * PS, PS);

    k_qk<<<512, 256>>>();
    k_A1t<<<dim3(64, BB), 256>>>(adj1, alpha);

    // GEMM2 + fused GEMM3 + fused BN-stat/pool
    mma_gemm2f<<<dim3(12, 1, BB), 256, smem_bytes>>>(
        c1hi, c1lo,
        h1, (long)NJ * PS,
        a1hi, a1lo,
        PS, b_c1,
        w_pool1, sbc, ssbc, dotb);

    k_hs4<<<PS / 256, 256>>>(gamma, beta, w_pool1, b_pool1);
    k_cls<<<BB, 256>>>(w_cls, b_cls, out);
}